// round 1
// baseline (speedup 1.0000x reference)
#include <cuda_runtime.h>
#include <cuda_bf16.h>

#define B     16384
#define D     1024
#define N_PER 8
#define G     (B / N_PER)      // 2048
#define MARGIN 0.5f
#define N_PAIRS 28.0f          // 8*7/2

// Per-group partial results (scratch; device globals are allowed)
__device__ float g_group_loss[G];

// One block per group. 256 threads; each thread owns 4 consecutive floats
// (one float4) of each of the 8 rows in the group.
__global__ __launch_bounds__(256) void group_kernel(const float* __restrict__ emb) {
    const int g   = blockIdx.x;
    const int tid = threadIdx.x;
    const int lane = tid & 31;
    const int warp = tid >> 5;

    // Base pointer for this group's 8 rows
    const float4* base = reinterpret_cast<const float4*>(emb + (size_t)g * N_PER * D);
    // row r, thread t -> float4 index r*(D/4) + t
    float4 v[N_PER];
    float  sq[N_PER];

#pragma unroll
    for (int r = 0; r < N_PER; r++) {
        v[r] = base[r * (D / 4) + tid];
        sq[r] = v[r].x * v[r].x + v[r].y * v[r].y + v[r].z * v[r].z + v[r].w * v[r].w;
    }

    // Warp-reduce each of the 8 per-row sums-of-squares
#pragma unroll
    for (int r = 0; r < N_PER; r++) {
#pragma unroll
        for (int off = 16; off > 0; off >>= 1)
            sq[r] += __shfl_down_sync(0xFFFFFFFFu, sq[r], off);
    }

    __shared__ float s_sq[8][N_PER];   // [warp][row]
    if (lane == 0) {
#pragma unroll
        for (int r = 0; r < N_PER; r++) s_sq[warp][r] = sq[r];
    }
    __syncthreads();

    __shared__ float s_inv[N_PER];
    if (tid < N_PER) {
        float s = 0.0f;
#pragma unroll
        for (int w = 0; w < 8; w++) s += s_sq[w][tid];
        float nrm = fmaxf(sqrtf(s), 1e-12f);
        s_inv[tid] = 1.0f / nrm;
    }
    __syncthreads();

    // Group sum vector (this thread's 4 components), then its squared norm
    float sx = 0.f, sy = 0.f, sz = 0.f, sw = 0.f;
#pragma unroll
    for (int r = 0; r < N_PER; r++) {
        const float inv = s_inv[r];
        sx += v[r].x * inv;
        sy += v[r].y * inv;
        sz += v[r].z * inv;
        sw += v[r].w * inv;
    }
    float part = sx * sx + sy * sy + sz * sz + sw * sw;

    // Block-reduce part -> ||s||^2
#pragma unroll
    for (int off = 16; off > 0; off >>= 1)
        part += __shfl_down_sync(0xFFFFFFFFu, part, off);

    __shared__ float s_part[8];
    if (lane == 0) s_part[warp] = part;
    __syncthreads();

    if (tid == 0) {
        float ss = 0.0f;
#pragma unroll
        for (int w = 0; w < 8; w++) ss += s_part[w];
        // mean_intra = 1 - (ss - 8)/56 ; loss = relu(mean_intra - margin)
        float mean_intra = 1.0f - (ss - (float)N_PER) / (2.0f * N_PAIRS);
        g_group_loss[g] = fmaxf(mean_intra - MARGIN, 0.0f);
    }
}

// Single-block deterministic reduction of the 2048 group losses -> mean
__global__ __launch_bounds__(256) void final_kernel(float* __restrict__ out) {
    const int tid = threadIdx.x;
    float acc = 0.0f;
#pragma unroll
    for (int i = tid; i < G; i += 256) acc += g_group_loss[i];

#pragma unroll
    for (int off = 16; off > 0; off >>= 1)
        acc += __shfl_down_sync(0xFFFFFFFFu, acc, off);

    __shared__ float s_part[8];
    if ((tid & 31) == 0) s_part[tid >> 5] = acc;
    __syncthreads();

    if (tid == 0) {
        float s = 0.0f;
#pragma unroll
        for (int w = 0; w < 8; w++) s += s_part[w];
        out[0] = s / (float)G;
    }
}

extern "C" void kernel_launch(void* const* d_in, const int* in_sizes, int n_in,
                              void* d_out, int out_size) {
    const float* emb = (const float*)d_in[0];
    // d_in[1] = labels (int32, arange(B)//8 — groups are contiguous blocks of 8;
    // grouping is implicit in the block->row mapping, labels unused)
    float* out = (float*)d_out;

    group_kernel<<<G, 256>>>(emb);
    final_kernel<<<1, 256>>>(out);
}